// round 4
// baseline (speedup 1.0000x reference)
#include <cuda_runtime.h>

// LightGCN pull-form: out = (x0+x1+x2+x3)/4, x_{l+1}[c] = sum_{e: col[e]=c} norm_e * x_l[row[e]]
// norm_e = rsqrt(deg[row]) * rsqrt(deg[col]), deg = in-degree over col (symmetric edge list).
// edge_index is int32 (JAX x64 disabled: astype(int64) is a silent no-op -> int32 on device).
// CSR over col rebuilt every call: graph-capturable, allocation-free.

static constexpr int    NU = 100000;
static constexpr int    NI = 50000;
static constexpr int    NN = NU + NI;        // 150000
static constexpr int    D  = 128;
static constexpr int    NE = 2000000;        // 2M directed edges
static constexpr size_t ND = (size_t)NN * D; // 19.2M floats (76.8 MB)

static constexpr int SCAN_B   = 1024;
static constexpr int NSCANBLK = (NN + SCAN_B - 1) / SCAN_B;  // 147
static_assert(NSCANBLK <= 256, "scan2 single block assumption");

// ---- static scratch (allocation-free rule) ----
__device__ float g_xbuf[2][ND];   // ping-pong layer features
__device__ float g_acc[ND];       // running sum x0+...+xl
__device__ float g_dinv[NN];
__device__ int   g_deg[NN];
__device__ int   g_rowptr[NN + 1];
__device__ int   g_cursor[NN];
__device__ int   g_bsum[256];
__device__ int2  g_edge[NE];      // {src, __float_as_int(norm)} grouped by dst

// ---------------- degree ----------------
__global__ void zero_deg_kernel() {
    int i = blockIdx.x * blockDim.x + threadIdx.x;
    if (i < NN) g_deg[i] = 0;
}

__global__ void deg_kernel(const int* __restrict__ col, int E) {
    int e = blockIdx.x * blockDim.x + threadIdx.x;
    if (e < E) {
        unsigned c = (unsigned)col[e];
        if (c < (unsigned)NN) atomicAdd(&g_deg[c], 1);
    }
}

__global__ void dinv_kernel() {
    int i = blockIdx.x * blockDim.x + threadIdx.x;
    if (i < NN) {
        int d = g_deg[i];
        g_dinv[i] = (d > 0) ? rsqrtf((float)d) : 0.0f;
    }
}

// ---------------- exclusive scan deg -> rowptr ----------------
__global__ void scan1_kernel() {
    __shared__ int s[SCAN_B];
    int tid = threadIdx.x;
    int i = blockIdx.x * SCAN_B + tid;
    int v = (i < NN) ? g_deg[i] : 0;
    s[tid] = v;
    __syncthreads();
    for (int off = 1; off < SCAN_B; off <<= 1) {
        int t = (tid >= off) ? s[tid - off] : 0;
        __syncthreads();
        s[tid] += t;
        __syncthreads();
    }
    if (i < NN) g_rowptr[i] = s[tid] - v;          // block-local exclusive
    if (tid == SCAN_B - 1) g_bsum[blockIdx.x] = s[tid];
}

__global__ void scan2_kernel() {
    __shared__ int s[256];
    int tid = threadIdx.x;
    int v = (tid < NSCANBLK) ? g_bsum[tid] : 0;
    s[tid] = v;
    __syncthreads();
    for (int off = 1; off < 256; off <<= 1) {
        int t = (tid >= off) ? s[tid - off] : 0;
        __syncthreads();
        s[tid] += t;
        __syncthreads();
    }
    g_bsum[tid] = s[tid] - v;                      // exclusive block offsets
}

__global__ void scan3_kernel(int E) {
    int i = blockIdx.x * blockDim.x + threadIdx.x;
    if (i < NN) {
        int rp = g_rowptr[i] + g_bsum[i / SCAN_B];
        g_rowptr[i] = rp;
        g_cursor[i] = rp;
    }
    if (i == 0) g_rowptr[NN] = E;
}

// ---------------- CSR fill (atomic placement) ----------------
__global__ void fill_kernel(const int* __restrict__ row,
                            const int* __restrict__ col, int E) {
    int e = blockIdx.x * blockDim.x + threadIdx.x;
    if (e < E) {
        unsigned r = (unsigned)row[e];
        unsigned c = (unsigned)col[e];
        if (r < (unsigned)NN && c < (unsigned)NN) {
            int pos = atomicAdd(&g_cursor[c], 1);
            float nrm = g_dinv[r] * g_dinv[c];
            g_edge[pos] = make_int2((int)r, __float_as_int(nrm));
        }
    }
}

// ---------------- x0 = concat(user, item); acc = x0 ----------------
__global__ void concat_kernel(const float* __restrict__ user_w,
                              const float* __restrict__ item_w) {
    size_t i = (size_t)blockIdx.x * blockDim.x + threadIdx.x; // float4 index
    const size_t n4  = ND / 4;
    const size_t nu4 = (size_t)NU * D / 4;
    if (i < n4) {
        float4 v = (i < nu4) ? ((const float4*)user_w)[i]
                             : ((const float4*)item_w)[i - nu4];
        ((float4*)g_xbuf[0])[i] = v;
        ((float4*)g_acc)[i]     = v;
    }
}

// ---------------- pull: x_out[n] = sum_nbrs norm * x_in[src]; acc += x_out ----------------
// One warp per destination node; lane L owns floats [4L, 4L+4).
__global__ void __launch_bounds__(256) pull_kernel(int lin, int lout) {
    int warp = (int)((blockIdx.x * (size_t)blockDim.x + threadIdx.x) >> 5);
    int lane = threadIdx.x & 31;
    if (warp >= NN) return;

    int beg = g_rowptr[warp];
    int end = g_rowptr[warp + 1];

    const float* __restrict__ xin = g_xbuf[lin];
    float4 acc  = make_float4(0.f, 0.f, 0.f, 0.f);
    float4 acc2 = make_float4(0.f, 0.f, 0.f, 0.f);

    int j = beg;
    // unroll by 2 for memory-level parallelism on the gathers
    for (; j + 1 < end; j += 2) {
        int2 e0 = g_edge[j];
        int2 e1 = g_edge[j + 1];
        float n0 = __int_as_float(e0.y);
        float n1 = __int_as_float(e1.y);
        float4 v0 = *(const float4*)(xin + (size_t)e0.x * D + lane * 4);
        float4 v1 = *(const float4*)(xin + (size_t)e1.x * D + lane * 4);
        acc.x  = fmaf(n0, v0.x, acc.x);  acc.y  = fmaf(n0, v0.y, acc.y);
        acc.z  = fmaf(n0, v0.z, acc.z);  acc.w  = fmaf(n0, v0.w, acc.w);
        acc2.x = fmaf(n1, v1.x, acc2.x); acc2.y = fmaf(n1, v1.y, acc2.y);
        acc2.z = fmaf(n1, v1.z, acc2.z); acc2.w = fmaf(n1, v1.w, acc2.w);
    }
    if (j < end) {
        int2 e0 = g_edge[j];
        float n0 = __int_as_float(e0.y);
        float4 v0 = *(const float4*)(xin + (size_t)e0.x * D + lane * 4);
        acc.x = fmaf(n0, v0.x, acc.x);  acc.y = fmaf(n0, v0.y, acc.y);
        acc.z = fmaf(n0, v0.z, acc.z);  acc.w = fmaf(n0, v0.w, acc.w);
    }
    acc.x += acc2.x; acc.y += acc2.y; acc.z += acc2.z; acc.w += acc2.w;

    size_t o = (size_t)warp * D + lane * 4;
    *(float4*)(g_xbuf[lout] + o) = acc;
    float4 a = *(float4*)(g_acc + o);
    a.x += acc.x; a.y += acc.y; a.z += acc.z; a.w += acc.w;
    *(float4*)(g_acc + o) = a;
}

// ---------------- final: out = 0.25 * acc ----------------
__global__ void final_kernel(float* __restrict__ out) {
    size_t i = (size_t)blockIdx.x * blockDim.x + threadIdx.x;
    if (i < ND / 4) {
        float4 a = ((const float4*)g_acc)[i];
        a.x *= 0.25f; a.y *= 0.25f; a.z *= 0.25f; a.w *= 0.25f;
        ((float4*)out)[i] = a;
    }
}

extern "C" void kernel_launch(void* const* d_in, const int* in_sizes, int n_in,
                              void* d_out, int out_size)
{
    const int*   edge_index = (const int*)d_in[0];   // [2, E] int32
    const float* user_w     = (const float*)d_in[1]; // [NU, D]
    const float* item_w     = (const float*)d_in[2]; // [NI, D]
    float*       out        = (float*)d_out;         // [NN, D]

    const int E = in_sizes[0] / 2;
    const int* row = edge_index;
    const int* col = edge_index + E;

    const int TB = 256;
    const int n4_blocks = (int)((ND / 4 + TB - 1) / TB);
    const int nn_blocks = (NN + TB - 1) / TB;
    const int e_blocks  = (E + TB - 1) / TB;
    const int pw_blocks = (NN + (TB / 32) - 1) / (TB / 32); // warp per node

    // degree + dinv
    zero_deg_kernel<<<nn_blocks, TB>>>();
    deg_kernel<<<e_blocks, TB>>>(col, E);
    dinv_kernel<<<nn_blocks, TB>>>();

    // CSR build
    scan1_kernel<<<NSCANBLK, SCAN_B>>>();
    scan2_kernel<<<1, 256>>>();
    scan3_kernel<<<nn_blocks, TB>>>(E);
    fill_kernel<<<e_blocks, TB>>>(row, col, E);

    // x0 and acc
    concat_kernel<<<n4_blocks, TB>>>(user_w, item_w);

    // 3 propagation layers (ping-pong buffers)
    pull_kernel<<<pw_blocks, TB>>>(0, 1);
    pull_kernel<<<pw_blocks, TB>>>(1, 0);
    pull_kernel<<<pw_blocks, TB>>>(0, 1);

    // out = mean of the 4
    final_kernel<<<n4_blocks, TB>>>(out);
}

// round 5
// speedup vs baseline: 1.4345x; 1.4345x over previous
#include <cuda_runtime.h>
#include <cuda_fp16.h>

// LightGCN pull-form: out = 0.25*(x0+x1+x2+x3), x_{l+1}[c] = sum_{e: col[e]=c} norm_e * x_l[row[e]]
// norm_e = rsqrt(deg[row])*rsqrt(deg[col]); deg = in-degree over col (symmetric list).
// edge_index is int32. CSR rebuilt every call (graph-capturable, allocation-free).
// Intermediate layer features stored fp16 (halves LTS gather traffic); accumulation fp32.

static constexpr int    NU = 100000;
static constexpr int    NI = 50000;
static constexpr int    NN = NU + NI;        // 150000
static constexpr int    D  = 128;
static constexpr int    NE = 2000000;
static constexpr size_t ND = (size_t)NN * D; // 19.2M elems

static constexpr int SCAN_B   = 1024;
static constexpr int NSCANBLK = (NN + SCAN_B - 1) / SCAN_B;  // 147
static_assert(NSCANBLK <= 256, "scan2 single block assumption");

// ---- static scratch ----
__device__ __half g_xh[4][ND];    // x0h..x3h fp16 features (38.4 MB each)
__device__ float  g_dinv[NN];
__device__ int    g_deg[NN];
__device__ int    g_rowptr[NN + 1];
__device__ int    g_cursor[NN];
__device__ int    g_bsum[256];
__device__ int2   g_edge[NE];     // {src, __float_as_int(norm)} grouped by dst

// ---- helpers: 4 halves <-> float4 via uint2 ----
__device__ __forceinline__ float4 h4_to_f4(uint2 v) {
    __half2 h0 = *reinterpret_cast<__half2*>(&v.x);
    __half2 h1 = *reinterpret_cast<__half2*>(&v.y);
    float2 f0 = __half22float2(h0);
    float2 f1 = __half22float2(h1);
    return make_float4(f0.x, f0.y, f1.x, f1.y);
}
__device__ __forceinline__ uint2 f4_to_h4(float4 v) {
    __half2 h0 = __floats2half2_rn(v.x, v.y);
    __half2 h1 = __floats2half2_rn(v.z, v.w);
    uint2 o;
    o.x = *reinterpret_cast<unsigned*>(&h0);
    o.y = *reinterpret_cast<unsigned*>(&h1);
    return o;
}

// ---------------- degree ----------------
__global__ void zero_deg_kernel() {
    int i = blockIdx.x * blockDim.x + threadIdx.x;
    if (i < NN) g_deg[i] = 0;
}

__global__ void deg_kernel(const int* __restrict__ col, int E) {
    int e = blockIdx.x * blockDim.x + threadIdx.x;
    if (e < E) {
        unsigned c = (unsigned)col[e];
        if (c < (unsigned)NN) atomicAdd(&g_deg[c], 1);
    }
}

__global__ void dinv_kernel() {
    int i = blockIdx.x * blockDim.x + threadIdx.x;
    if (i < NN) {
        int d = g_deg[i];
        g_dinv[i] = (d > 0) ? rsqrtf((float)d) : 0.0f;
    }
}

// ---------------- exclusive scan deg -> rowptr ----------------
__global__ void scan1_kernel() {
    __shared__ int s[SCAN_B];
    int tid = threadIdx.x;
    int i = blockIdx.x * SCAN_B + tid;
    int v = (i < NN) ? g_deg[i] : 0;
    s[tid] = v;
    __syncthreads();
    for (int off = 1; off < SCAN_B; off <<= 1) {
        int t = (tid >= off) ? s[tid - off] : 0;
        __syncthreads();
        s[tid] += t;
        __syncthreads();
    }
    if (i < NN) g_rowptr[i] = s[tid] - v;
    if (tid == SCAN_B - 1) g_bsum[blockIdx.x] = s[tid];
}

__global__ void scan2_kernel() {
    __shared__ int s[256];
    int tid = threadIdx.x;
    int v = (tid < NSCANBLK) ? g_bsum[tid] : 0;
    s[tid] = v;
    __syncthreads();
    for (int off = 1; off < 256; off <<= 1) {
        int t = (tid >= off) ? s[tid - off] : 0;
        __syncthreads();
        s[tid] += t;
        __syncthreads();
    }
    g_bsum[tid] = s[tid] - v;
}

__global__ void scan3_kernel(int E) {
    int i = blockIdx.x * blockDim.x + threadIdx.x;
    if (i < NN) {
        int rp = g_rowptr[i] + g_bsum[i / SCAN_B];
        g_rowptr[i] = rp;
        g_cursor[i] = rp;
    }
    if (i == 0) g_rowptr[NN] = E;
}

// ---------------- CSR fill ----------------
__global__ void fill_kernel(const int* __restrict__ row,
                            const int* __restrict__ col, int E) {
    int e = blockIdx.x * blockDim.x + threadIdx.x;
    if (e < E) {
        unsigned r = (unsigned)row[e];
        unsigned c = (unsigned)col[e];
        if (r < (unsigned)NN && c < (unsigned)NN) {
            int pos = atomicAdd(&g_cursor[c], 1);
            float nrm = g_dinv[r] * g_dinv[c];
            g_edge[pos] = make_int2((int)r, __float_as_int(nrm));
        }
    }
}

// ---------------- x0h = fp16(concat(user, item)) ----------------
__global__ void cvt0_kernel(const float* __restrict__ user_w,
                            const float* __restrict__ item_w) {
    size_t i = (size_t)blockIdx.x * blockDim.x + threadIdx.x; // float4 index
    const size_t n4  = ND / 4;
    const size_t nu4 = (size_t)NU * (D / 4);
    if (i < n4) {
        float4 v = (i < nu4) ? ((const float4*)user_w)[i]
                             : ((const float4*)item_w)[i - nu4];
        ((uint2*)g_xh[0])[i] = f4_to_h4(v);
    }
}

// ---------------- pull: xh[lout][n] = fp16( sum_nbrs norm * fp32(xh[lin][src]) ) ----------------
// One warp per destination node; lane L owns halves [4L, 4L+4)  (one uint2 per lane).
__global__ void __launch_bounds__(256) pull_kernel(int lin, int lout) {
    int node = (int)((blockIdx.x * (size_t)blockDim.x + threadIdx.x) >> 5);
    int lane = threadIdx.x & 31;
    if (node >= NN) return;

    int beg = g_rowptr[node];
    int end = g_rowptr[node + 1];

    const uint2* __restrict__ xin = (const uint2*)g_xh[lin]; // 32 uint2 per row
    float4 a0 = make_float4(0.f, 0.f, 0.f, 0.f);
    float4 a1 = make_float4(0.f, 0.f, 0.f, 0.f);

    int j = beg;
    for (; j + 3 < end; j += 4) {
        int2 e0 = g_edge[j];
        int2 e1 = g_edge[j + 1];
        int2 e2 = g_edge[j + 2];
        int2 e3 = g_edge[j + 3];
        uint2 r0 = xin[(size_t)e0.x * 32 + lane];
        uint2 r1 = xin[(size_t)e1.x * 32 + lane];
        uint2 r2 = xin[(size_t)e2.x * 32 + lane];
        uint2 r3 = xin[(size_t)e3.x * 32 + lane];
        float n0 = __int_as_float(e0.y), n1 = __int_as_float(e1.y);
        float n2 = __int_as_float(e2.y), n3 = __int_as_float(e3.y);
        float4 v0 = h4_to_f4(r0), v1 = h4_to_f4(r1);
        float4 v2 = h4_to_f4(r2), v3 = h4_to_f4(r3);
        a0.x = fmaf(n0, v0.x, a0.x); a0.y = fmaf(n0, v0.y, a0.y);
        a0.z = fmaf(n0, v0.z, a0.z); a0.w = fmaf(n0, v0.w, a0.w);
        a1.x = fmaf(n1, v1.x, a1.x); a1.y = fmaf(n1, v1.y, a1.y);
        a1.z = fmaf(n1, v1.z, a1.z); a1.w = fmaf(n1, v1.w, a1.w);
        a0.x = fmaf(n2, v2.x, a0.x); a0.y = fmaf(n2, v2.y, a0.y);
        a0.z = fmaf(n2, v2.z, a0.z); a0.w = fmaf(n2, v2.w, a0.w);
        a1.x = fmaf(n3, v3.x, a1.x); a1.y = fmaf(n3, v3.y, a1.y);
        a1.z = fmaf(n3, v3.z, a1.z); a1.w = fmaf(n3, v3.w, a1.w);
    }
    for (; j < end; j++) {
        int2 e0 = g_edge[j];
        uint2 r0 = xin[(size_t)e0.x * 32 + lane];
        float n0 = __int_as_float(e0.y);
        float4 v0 = h4_to_f4(r0);
        a0.x = fmaf(n0, v0.x, a0.x); a0.y = fmaf(n0, v0.y, a0.y);
        a0.z = fmaf(n0, v0.z, a0.z); a0.w = fmaf(n0, v0.w, a0.w);
    }
    a0.x += a1.x; a0.y += a1.y; a0.z += a1.z; a0.w += a1.w;

    ((uint2*)g_xh[lout])[(size_t)node * 32 + lane] = f4_to_h4(a0);
}

// ---------------- final: out = 0.25 * (x0_fp32 + x1h + x2h + x3h) ----------------
__global__ void final_kernel(const float* __restrict__ user_w,
                             const float* __restrict__ item_w,
                             float* __restrict__ out) {
    size_t i = (size_t)blockIdx.x * blockDim.x + threadIdx.x; // float4 index
    const size_t n4  = ND / 4;
    const size_t nu4 = (size_t)NU * (D / 4);
    if (i < n4) {
        float4 x0 = (i < nu4) ? ((const float4*)user_w)[i]
                              : ((const float4*)item_w)[i - nu4];
        float4 x1 = h4_to_f4(((const uint2*)g_xh[1])[i]);
        float4 x2 = h4_to_f4(((const uint2*)g_xh[2])[i]);
        float4 x3 = h4_to_f4(((const uint2*)g_xh[3])[i]);
        float4 o;
        o.x = 0.25f * (x0.x + x1.x + x2.x + x3.x);
        o.y = 0.25f * (x0.y + x1.y + x2.y + x3.y);
        o.z = 0.25f * (x0.z + x1.z + x2.z + x3.z);
        o.w = 0.25f * (x0.w + x1.w + x2.w + x3.w);
        ((float4*)out)[i] = o;
    }
}

extern "C" void kernel_launch(void* const* d_in, const int* in_sizes, int n_in,
                              void* d_out, int out_size)
{
    const int*   edge_index = (const int*)d_in[0];   // [2, E] int32
    const float* user_w     = (const float*)d_in[1]; // [NU, D]
    const float* item_w     = (const float*)d_in[2]; // [NI, D]
    float*       out        = (float*)d_out;         // [NN, D]

    const int E = in_sizes[0] / 2;
    const int* row = edge_index;
    const int* col = edge_index + E;

    const int TB = 256;
    const int n4_blocks = (int)((ND / 4 + TB - 1) / TB);
    const int nn_blocks = (NN + TB - 1) / TB;
    const int e_blocks  = (E + TB - 1) / TB;
    const int pw_blocks = (NN + (TB / 32) - 1) / (TB / 32);

    // degree + dinv
    zero_deg_kernel<<<nn_blocks, TB>>>();
    deg_kernel<<<e_blocks, TB>>>(col, E);
    dinv_kernel<<<nn_blocks, TB>>>();

    // CSR build
    scan1_kernel<<<NSCANBLK, SCAN_B>>>();
    scan2_kernel<<<1, 256>>>();
    scan3_kernel<<<nn_blocks, TB>>>(E);
    fill_kernel<<<e_blocks, TB>>>(row, col, E);

    // x0h (fp16 copy of inputs for gathering)
    cvt0_kernel<<<n4_blocks, TB>>>(user_w, item_w);

    // 3 propagation layers, each into its own fp16 buffer
    pull_kernel<<<pw_blocks, TB>>>(0, 1);
    pull_kernel<<<pw_blocks, TB>>>(1, 2);
    pull_kernel<<<pw_blocks, TB>>>(2, 3);

    // out = mean of the 4 (x0 read in fp32 from the inputs)
    final_kernel<<<n4_blocks, TB>>>(user_w, item_w, out);
}

// round 6
// speedup vs baseline: 1.5555x; 1.0844x over previous
#include <cuda_runtime.h>
#include <cuda_fp16.h>

// LightGCN pull-form: out = 0.25*(x0+x1+x2+x3), x_{l+1}[c] = sum_{e: col[e]=c} norm_e * x_l[row[e]]
// norm_e = rsqrt(deg[row])*rsqrt(deg[col]); deg = in-degree over col (symmetric list).
// edge_index int32. CSR (src-only payload) rebuilt every call; fp16 feature storage, fp32 math.
// Pull kernel: warp handles one dst node, HALF-WARP per edge (lane slice = 16B uint4).

static constexpr int    NU = 100000;
static constexpr int    NI = 50000;
static constexpr int    NN = NU + NI;        // 150000
static constexpr int    D  = 128;
static constexpr int    NE = 2000000;
static constexpr size_t ND = (size_t)NN * D; // 19.2M elems

static constexpr int SCAN_B   = 1024;
static constexpr int NSCANBLK = (NN + SCAN_B - 1) / SCAN_B;  // 147
static_assert(NSCANBLK <= 256, "scan2 single block assumption");

// ---- static scratch ----
__device__ __half g_xh[4][ND];    // x0h..x3h fp16 features (38.4 MB each)
__device__ float  g_dinv[NN];
__device__ int    g_deg[NN];
__device__ int    g_rowptr[NN + 1];
__device__ int    g_cursor[NN];
__device__ int    g_bsum[256];
__device__ int    g_edge[NE];     // src only, grouped by dst

// ---- helpers ----
__device__ __forceinline__ float4 h4_to_f4(uint2 v) {
    float2 f0 = __half22float2(*reinterpret_cast<__half2*>(&v.x));
    float2 f1 = __half22float2(*reinterpret_cast<__half2*>(&v.y));
    return make_float4(f0.x, f0.y, f1.x, f1.y);
}
__device__ __forceinline__ uint2 f4_to_h4(float4 v) {
    __half2 h0 = __floats2half2_rn(v.x, v.y);
    __half2 h1 = __floats2half2_rn(v.z, v.w);
    uint2 o;
    o.x = *reinterpret_cast<unsigned*>(&h0);
    o.y = *reinterpret_cast<unsigned*>(&h1);
    return o;
}

// ---------------- degree ----------------
__global__ void deg_kernel(const int* __restrict__ col, int E) {
    int e = blockIdx.x * blockDim.x + threadIdx.x;
    if (e < E) {
        unsigned c = (unsigned)col[e];
        if (c < (unsigned)NN) atomicAdd(&g_deg[c], 1);
    }
}

// ---------------- scan part 1 (+ fused dinv) ----------------
__global__ void scan1_kernel() {
    __shared__ int s[SCAN_B];
    int tid = threadIdx.x;
    int i = blockIdx.x * SCAN_B + tid;
    int v = (i < NN) ? g_deg[i] : 0;
    if (i < NN) g_dinv[i] = (v > 0) ? rsqrtf((float)v) : 0.0f;
    s[tid] = v;
    __syncthreads();
    for (int off = 1; off < SCAN_B; off <<= 1) {
        int t = (tid >= off) ? s[tid - off] : 0;
        __syncthreads();
        s[tid] += t;
        __syncthreads();
    }
    if (i < NN) g_rowptr[i] = s[tid] - v;
    if (tid == SCAN_B - 1) g_bsum[blockIdx.x] = s[tid];
}

__global__ void scan2_kernel() {
    __shared__ int s[256];
    int tid = threadIdx.x;
    int v = (tid < NSCANBLK) ? g_bsum[tid] : 0;
    s[tid] = v;
    __syncthreads();
    for (int off = 1; off < 256; off <<= 1) {
        int t = (tid >= off) ? s[tid - off] : 0;
        __syncthreads();
        s[tid] += t;
        __syncthreads();
    }
    g_bsum[tid] = s[tid] - v;
}

__global__ void scan3_kernel(int E) {
    int i = blockIdx.x * blockDim.x + threadIdx.x;
    if (i < NN) {
        int rp = g_rowptr[i] + g_bsum[i / SCAN_B];
        g_rowptr[i] = rp;
        g_cursor[i] = rp;
    }
    if (i == 0) g_rowptr[NN] = E;
}

// ---------------- CSR fill (src only) ----------------
__global__ void fill_kernel(const int* __restrict__ row,
                            const int* __restrict__ col, int E) {
    int e = blockIdx.x * blockDim.x + threadIdx.x;
    if (e < E) {
        unsigned r = (unsigned)row[e];
        unsigned c = (unsigned)col[e];
        if (r < (unsigned)NN && c < (unsigned)NN) {
            int pos = atomicAdd(&g_cursor[c], 1);
            g_edge[pos] = (int)r;
        }
    }
}

// ---------------- x0h = fp16(concat(user, item)) ----------------
__global__ void cvt0_kernel(const float* __restrict__ user_w,
                            const float* __restrict__ item_w) {
    size_t i = (size_t)blockIdx.x * blockDim.x + threadIdx.x; // float4 index
    const size_t n4  = ND / 4;
    const size_t nu4 = (size_t)NU * (D / 4);
    if (i < n4) {
        float4 v = (i < nu4) ? ((const float4*)user_w)[i]
                             : ((const float4*)item_w)[i - nu4];
        ((uint2*)g_xh[0])[i] = f4_to_h4(v);
    }
}

// ---------------- pull: xh[lout][n] = fp16( sum_nbrs norm * fp32(xh[lin][src]) ) ----------------
// One warp per dst node; half-warp per edge; lane slice = 16 B (uint4 = 8 halves).
__global__ void __launch_bounds__(256) pull_kernel(int lin, int lout) {
    int node = (int)((blockIdx.x * (size_t)blockDim.x + threadIdx.x) >> 5);
    int lane = threadIdx.x & 31;
    if (node >= NN) return;

    int beg = g_rowptr[node];
    int end = g_rowptr[node + 1];
    float dn = g_dinv[node];

    int half = lane >> 4;   // which edge of the pair
    int sub  = lane & 15;   // 16B slice within the 256B row

    const uint4* __restrict__ xin = (const uint4*)g_xh[lin]; // 16 uint4 per row

    float a0 = 0.f, a1 = 0.f, a2 = 0.f, a3 = 0.f;
    float a4 = 0.f, a5 = 0.f, a6 = 0.f, a7 = 0.f;

    #pragma unroll 2
    for (int j = beg; j < end; j += 2) {
        int jj = j + half;
        float nrm = 0.f;
        uint4 r = make_uint4(0u, 0u, 0u, 0u);
        if (jj < end) {
            int src = g_edge[jj];
            nrm = g_dinv[src] * dn;
            r = xin[(size_t)src * 16 + sub];
        }
        float2 f0 = __half22float2(*reinterpret_cast<__half2*>(&r.x));
        float2 f1 = __half22float2(*reinterpret_cast<__half2*>(&r.y));
        float2 f2 = __half22float2(*reinterpret_cast<__half2*>(&r.z));
        float2 f3 = __half22float2(*reinterpret_cast<__half2*>(&r.w));
        a0 = fmaf(nrm, f0.x, a0); a1 = fmaf(nrm, f0.y, a1);
        a2 = fmaf(nrm, f1.x, a2); a3 = fmaf(nrm, f1.y, a3);
        a4 = fmaf(nrm, f2.x, a4); a5 = fmaf(nrm, f2.y, a5);
        a6 = fmaf(nrm, f3.x, a6); a7 = fmaf(nrm, f3.y, a7);
    }

    // combine the two half-warps (lane L and L+16 hold the same feature slice)
    a0 += __shfl_xor_sync(0xFFFFFFFFu, a0, 16);
    a1 += __shfl_xor_sync(0xFFFFFFFFu, a1, 16);
    a2 += __shfl_xor_sync(0xFFFFFFFFu, a2, 16);
    a3 += __shfl_xor_sync(0xFFFFFFFFu, a3, 16);
    a4 += __shfl_xor_sync(0xFFFFFFFFu, a4, 16);
    a5 += __shfl_xor_sync(0xFFFFFFFFu, a5, 16);
    a6 += __shfl_xor_sync(0xFFFFFFFFu, a6, 16);
    a7 += __shfl_xor_sync(0xFFFFFFFFu, a7, 16);

    if (half == 0) {
        __half2 h0 = __floats2half2_rn(a0, a1);
        __half2 h1 = __floats2half2_rn(a2, a3);
        __half2 h2 = __floats2half2_rn(a4, a5);
        __half2 h3 = __floats2half2_rn(a6, a7);
        uint4 o;
        o.x = *reinterpret_cast<unsigned*>(&h0);
        o.y = *reinterpret_cast<unsigned*>(&h1);
        o.z = *reinterpret_cast<unsigned*>(&h2);
        o.w = *reinterpret_cast<unsigned*>(&h3);
        ((uint4*)g_xh[lout])[(size_t)node * 16 + sub] = o;
    }
}

// ---------------- final: out = 0.25 * (x0_fp32 + x1h + x2h + x3h) ----------------
__global__ void final_kernel(const float* __restrict__ user_w,
                             const float* __restrict__ item_w,
                             float* __restrict__ out) {
    size_t i = (size_t)blockIdx.x * blockDim.x + threadIdx.x; // float4 index
    const size_t n4  = ND / 4;
    const size_t nu4 = (size_t)NU * (D / 4);
    if (i < n4) {
        float4 x0 = (i < nu4) ? ((const float4*)user_w)[i]
                              : ((const float4*)item_w)[i - nu4];
        float4 x1 = h4_to_f4(((const uint2*)g_xh[1])[i]);
        float4 x2 = h4_to_f4(((const uint2*)g_xh[2])[i]);
        float4 x3 = h4_to_f4(((const uint2*)g_xh[3])[i]);
        float4 o;
        o.x = 0.25f * (x0.x + x1.x + x2.x + x3.x);
        o.y = 0.25f * (x0.y + x1.y + x2.y + x3.y);
        o.z = 0.25f * (x0.z + x1.z + x2.z + x3.z);
        o.w = 0.25f * (x0.w + x1.w + x2.w + x3.w);
        ((float4*)out)[i] = o;
    }
}

extern "C" void kernel_launch(void* const* d_in, const int* in_sizes, int n_in,
                              void* d_out, int out_size)
{
    const int*   edge_index = (const int*)d_in[0];   // [2, E] int32
    const float* user_w     = (const float*)d_in[1]; // [NU, D]
    const float* item_w     = (const float*)d_in[2]; // [NI, D]
    float*       out        = (float*)d_out;         // [NN, D]

    const int E = in_sizes[0] / 2;
    const int* row = edge_index;
    const int* col = edge_index + E;

    const int TB = 256;
    const int n4_blocks = (int)((ND / 4 + TB - 1) / TB);
    const int nn_blocks = (NN + TB - 1) / TB;
    const int e_blocks  = (E + TB - 1) / TB;
    const int pw_blocks = (NN + (TB / 32) - 1) / (TB / 32);

    // zero degree via captured memset (cheaper than a kernel)
    void* deg_ptr = nullptr;
    cudaGetSymbolAddress(&deg_ptr, g_deg);
    cudaMemsetAsync(deg_ptr, 0, NN * sizeof(int));

    // degree -> (scan + dinv) -> rowptr -> fill
    deg_kernel<<<e_blocks, TB>>>(col, E);
    scan1_kernel<<<NSCANBLK, SCAN_B>>>();
    scan2_kernel<<<1, 256>>>();
    scan3_kernel<<<nn_blocks, TB>>>(E);
    fill_kernel<<<e_blocks, TB>>>(row, col, E);

    // x0h (fp16 copy of inputs for gathering)
    cvt0_kernel<<<n4_blocks, TB>>>(user_w, item_w);

    // 3 propagation layers, each into its own fp16 buffer
    pull_kernel<<<pw_blocks, TB>>>(0, 1);
    pull_kernel<<<pw_blocks, TB>>>(1, 2);
    pull_kernel<<<pw_blocks, TB>>>(2, 3);

    // out = mean of the 4 (x0 read in fp32 from the inputs)
    final_kernel<<<n4_blocks, TB>>>(user_w, item_w, out);
}